// round 9
// baseline (speedup 1.0000x reference)
#include <cuda_runtime.h>
#include <cuda_fp16.h>
#include <cstdint>

// SDPA B=4,H=16,S=2048,D=64 fp32. scores = QK^T * 4096 -> one-hot softmax.
// R9: occupancy push. Kernel is latency-bound (R6/R8 work cuts gave <5%):
// force 3 CTAs/SM via __launch_bounds__(256,3) (regs<=85). Epilogue es/ke
// arrays moved to smem (reusing the cp.async staging ring after wait_all)
// so they don't set the register high-water mark. Structure otherwise = R8.

#define S_LEN 2048
#define HDIM  64
#define TQ    128
#define THREADS 256
#define TKT   64
#define NKT   (S_LEN / TKT)
#define N_BH  64
#define WINAPPROX 0.12f
#define LSCALE 4096.0f
#define NCAND 32

#define TILE_WORDS 2048                  // 8 KB per stage
#define NSTAGE 4

#define W_STG 0
#define W_CS  (W_STG + NSTAGE * TILE_WORDS)
#define W_CK  (W_CS + TQ * NCAND)
#define W_CNT (W_CK + TQ * NCAND)
#define SMEM_WORDS (W_CNT + TQ)
#define SMEM_BYTES (SMEM_WORDS * 4)      // ~64.5 KB -> 3 CTAs/SM

typedef unsigned long long u64;

__device__ static uint32_t g_kscr[(size_t)N_BH * NKT * TILE_WORDS];

__device__ __forceinline__ void mma_f16(float& d0, float& d1, float& d2, float& d3,
                                        uint32_t a0, uint32_t a1, uint32_t a2, uint32_t a3,
                                        uint32_t b0, uint32_t b1) {
    asm volatile(
        "mma.sync.aligned.m16n8k16.row.col.f32.f16.f16.f32 "
        "{%0,%1,%2,%3}, {%4,%5,%6,%7}, {%8,%9}, {%0,%1,%2,%3};"
        : "+f"(d0), "+f"(d1), "+f"(d2), "+f"(d3)
        : "r"(a0), "r"(a1), "r"(a2), "r"(a3), "r"(b0), "r"(b1));
}
__device__ __forceinline__ uint32_t f16x2(float lo, float hi) {
    uint32_t d;
    asm("cvt.rn.f16x2.f32 %0, %1, %2;" : "=r"(d) : "f"(hi), "f"(lo));
    return d;
}
__device__ __forceinline__ u64 ffma2(u64 a, u64 b, u64 c) {
    u64 d;
    asm("fma.rn.f32x2 %0, %1, %2, %3;" : "=l"(d) : "l"(a), "l"(b), "l"(c));
    return d;
}
__device__ __forceinline__ u64 fadd2(u64 a, u64 b) {
    u64 d;
    asm("add.rn.f32x2 %0, %1, %2;" : "=l"(d) : "l"(a), "l"(b));
    return d;
}
__device__ __forceinline__ float hsum2(u64 a) {
    float x, y;
    asm("mov.b64 {%0, %1}, %2;" : "=f"(x), "=f"(y) : "l"(a));
    return x + y;
}
__device__ __forceinline__ u64 pack2(float x, float y) {
    u64 d;
    asm("mov.b64 %0, {%1, %2};" : "=l"(d) : "f"(x), "f"(y));
    return d;
}
__device__ __forceinline__ void cp16(uint32_t saddr, const void* g) {
    asm volatile("cp.async.cg.shared.global [%0], [%1], 16;" :: "r"(saddr), "l"(g));
}

__global__ void __launch_bounds__(256)
k_convert_kernel(const float* __restrict__ K) {
    const int x = blockIdx.x;
    const int tid = threadIdx.x;
    const int bh = x / NKT, kt = x - bh * NKT;
    const float* kt_base = K + ((long)bh * S_LEN + (long)kt * TKT) * HDIM;
    uint32_t* dst = g_kscr + (size_t)x * TILE_WORDS;
#pragma unroll
    for (int i = 0; i < TILE_WORDS / 256; i++) {
        const int w = i * 256 + tid;
        const int b = w >> 7, iw = w & 127;
        const int nt = b >> 1, p = b & 1;
        const int n = nt * 8 + (iw >> 4);
        const int c = (iw >> 2) & 3, q = iw & 3;
        const int ks = 2 * p + (q >> 1);
        const int d2 = 8 * ks + 4 * (q & 1) + c;
        const float2 v = *(const float2*)(kt_base + n * HDIM + 2 * d2);
        dst[w] = f16x2(v.x, v.y);
    }
}

__global__ void __launch_bounds__(THREADS, 3)
sdpa_r9_kernel(const float* __restrict__ Q,
               const float* __restrict__ K,
               const float* __restrict__ V,
               float* __restrict__ O) {
    extern __shared__ float sm[];
    float* csq = sm + W_CS;
    int*   ckq = (int*)(sm + W_CK);
    int*   cntq = (int*)(sm + W_CNT);
    uint32_t sb;
    asm("{ .reg .u64 t; cvta.to.shared.u64 t, %1; cvt.u32.u64 %0, t; }" : "=r"(sb) : "l"(sm));

    const int tid  = threadIdx.x;
    const int lane = tid & 31;
    const int warp = tid >> 5;
    const int g    = lane >> 2;
    const int t    = lane & 3;
    const int bh   = blockIdx.y;
    const long bhoff = (long)bh * S_LEN * HDIM;
    const float* kb = K + bhoff;
    const float* vb = V + bhoff;
    const uint32_t* gsrc = g_kscr + (size_t)bh * NKT * TILE_WORDS;

    if (tid < TQ) cntq[tid] = 0;

#pragma unroll
    for (int s = 0; s < NSTAGE - 1; s++) {
        const uint32_t sa = sb + (W_STG + s * TILE_WORDS) * 4 + tid * 32;
        const uint32_t* gp = gsrc + s * TILE_WORDS + tid * 8;
        cp16(sa, gp);
        cp16(sa + 16, gp + 4);
        asm volatile("cp.async.commit_group;" ::: "memory");
    }

    uint32_t af[4][4];
    {
        const float* r0 = Q + ((long)bh * S_LEN + blockIdx.x * TQ + warp * 16 + g) * HDIM;
        const float* r1 = r0 + 8 * HDIM;
#pragma unroll
        for (int s = 0; s < 4; s++) {
            const int c = 16 * s + 2 * t;
            float2 v;
            v = *(const float2*)(r0 + c);     af[s][0] = f16x2(v.x, v.y);
            v = *(const float2*)(r1 + c);     af[s][1] = f16x2(v.x, v.y);
            v = *(const float2*)(r0 + c + 8); af[s][2] = f16x2(v.x, v.y);
            v = *(const float2*)(r1 + c + 8); af[s][3] = f16x2(v.x, v.y);
        }
    }

    float m0 = -INFINITY, thr0 = -INFINITY;
    float m1 = -INFINITY, thr1 = -INFINITY;
    const int q0 = warp * 16 + g;
    const int q1 = q0 + 8;

    for (int kt = 0; kt < NKT; kt++) {
        asm volatile("cp.async.wait_group 2;" ::: "memory");
        __syncthreads();

        if (kt + 3 < NKT) {
            const int s = (kt + 3) & (NSTAGE - 1);
            const uint32_t sa = sb + (W_STG + s * TILE_WORDS) * 4 + tid * 32;
            const uint32_t* gp = gsrc + (kt + 3) * TILE_WORDS + tid * 8;
            cp16(sa, gp);
            cp16(sa + 16, gp + 4);
        }
        asm volatile("cp.async.commit_group;" ::: "memory");

        const uint32_t* sKB = (const uint32_t*)sm + W_STG + (kt & (NSTAGE - 1)) * TILE_WORDS;

        float acc[8][4];
#pragma unroll
        for (int nt = 0; nt < 8; nt++)
#pragma unroll
            for (int e = 0; e < 4; e++) acc[nt][e] = 0.0f;

#pragma unroll
        for (int p = 0; p < 2; p++) {
#pragma unroll
            for (int ng = 0; ng < 2; ng++) {
                uint4 bf[4];
#pragma unroll
                for (int i = 0; i < 4; i++)
                    bf[i] = *(const uint4*)(sKB + (((ng * 4 + i) * 2 + p) << 7) + lane * 4);
#pragma unroll
                for (int i = 0; i < 4; i++) {
                    const int nt = ng * 4 + i;
                    mma_f16(acc[nt][0], acc[nt][1], acc[nt][2], acc[nt][3],
                            af[2 * p][0], af[2 * p][1], af[2 * p][2], af[2 * p][3],
                            bf[i].x, bf[i].y);
                }
#pragma unroll
                for (int i = 0; i < 4; i++) {
                    const int nt = ng * 4 + i;
                    mma_f16(acc[nt][0], acc[nt][1], acc[nt][2], acc[nt][3],
                            af[2 * p + 1][0], af[2 * p + 1][1],
                            af[2 * p + 1][2], af[2 * p + 1][3],
                            bf[i].z, bf[i].w);
                }
            }
        }

        float mx0 = fmaxf(acc[0][0], acc[0][1]);
        float mx1 = fmaxf(acc[0][2], acc[0][3]);
#pragma unroll
        for (int nt = 1; nt < 8; nt++) {
            mx0 = fmaxf(mx0, fmaxf(acc[nt][0], acc[nt][1]));
            mx1 = fmaxf(mx1, fmaxf(acc[nt][2], acc[nt][3]));
        }
        mx0 = fmaxf(mx0, __shfl_xor_sync(0xFFFFFFFFu, mx0, 1));
        mx0 = fmaxf(mx0, __shfl_xor_sync(0xFFFFFFFFu, mx0, 2));
        mx1 = fmaxf(mx1, __shfl_xor_sync(0xFFFFFFFFu, mx1, 1));
        mx1 = fmaxf(mx1, __shfl_xor_sync(0xFFFFFFFFu, mx1, 2));

        const int kbase = kt * TKT;
        if (mx0 > thr0) {
            m0 = fmaxf(m0, mx0);
            thr0 = m0 - WINAPPROX;
#pragma unroll
            for (int nt = 0; nt < 8; nt++) {
#pragma unroll
                for (int e = 0; e < 2; e++) {
                    const float s = acc[nt][e];
                    if (s > thr0) {
                        const int slot = atomicAdd(&cntq[q0], 1);
                        if (slot < NCAND) {
                            csq[q0 * NCAND + slot] = s;
                            ckq[q0 * NCAND + slot] = kbase + nt * 8 + 2 * t + e;
                        }
                    }
                }
            }
        }
        if (mx1 > thr1) {
            m1 = fmaxf(m1, mx1);
            thr1 = m1 - WINAPPROX;
#pragma unroll
            for (int nt = 0; nt < 8; nt++) {
#pragma unroll
                for (int e = 0; e < 2; e++) {
                    const float s = acc[nt][2 + e];
                    if (s > thr1) {
                        const int slot = atomicAdd(&cntq[q1], 1);
                        if (slot < NCAND) {
                            csq[q1 * NCAND + slot] = s;
                            ckq[q1 * NCAND + slot] = kbase + nt * 8 + 2 * t + e;
                        }
                    }
                }
            }
        }
    }

    // drain remaining cp.async groups before reusing the staging ring
    asm volatile("cp.async.wait_group 0;" ::: "memory");
    __syncthreads();

    // ---- epilogue: exact fp32 rescore; es/ke live in reused staging smem ----
    if (tid < TQ) {
        float* es = sm + W_STG;                       // [i*TQ + tid], 16 KB
        int*   ke = (int*)(sm + W_STG) + NCAND * TQ;  // [i*TQ + tid], 16 KB

        const long qrow = (long)bh * S_LEN + blockIdx.x * TQ + tid;
        const u64* qg = (const u64*)(Q + qrow * HDIM);
        u64 q2[HDIM / 2];
#pragma unroll
        for (int j = 0; j < HDIM / 2; j++) q2[j] = qg[j];

        int nc = cntq[tid];
        if (nc > NCAND) nc = NCAND;
        float em = -INFINITY;
        for (int i = 0; i < nc; i++) {
            const int key = ckq[tid * NCAND + i];
            ke[i * TQ + tid] = key;
            const u64* kr = (const u64*)(kb + (long)key * HDIM);
            u64 a0 = 0ULL, a1 = 0ULL, a2 = 0ULL, a3 = 0ULL;
#pragma unroll
            for (int j = 0; j < 8; j++) {
                a0 = ffma2(q2[4 * j + 0], kr[4 * j + 0], a0);
                a1 = ffma2(q2[4 * j + 1], kr[4 * j + 1], a1);
                a2 = ffma2(q2[4 * j + 2], kr[4 * j + 2], a2);
                a3 = ffma2(q2[4 * j + 3], kr[4 * j + 3], a3);
            }
            const float e = hsum2(fadd2(fadd2(a0, a1), fadd2(a2, a3)));
            es[i * TQ + tid] = e;
            em = fmaxf(em, e);
        }

        u64 o2[HDIM / 2];
#pragma unroll
        for (int j = 0; j < HDIM / 2; j++) o2[j] = 0ULL;
        float lsum = 0.0f;
        for (int i = 0; i < nc; i++) {
            const float w = __expf(LSCALE * (es[i * TQ + tid] - em));
            if (w > 1e-9f) {
                lsum += w;
                const u64* v2 = (const u64*)(vb + (long)ke[i * TQ + tid] * HDIM);
                const u64 w2 = pack2(w, w);
#pragma unroll
                for (int j = 0; j < HDIM / 2; j++) o2[j] = ffma2(w2, v2[j], o2[j]);
            }
        }
        const float inv = 1.0f / lsum;
        const u64 inv2 = pack2(inv, inv);
        u64* og = (u64*)(O + qrow * HDIM);
#pragma unroll
        for (int j = 0; j < HDIM / 2; j++) {
            u64 r;
            asm("mul.rn.f32x2 %0, %1, %2;" : "=l"(r) : "l"(o2[j]), "l"(inv2));
            og[j] = r;
        }
    }
}

extern "C" void kernel_launch(void* const* d_in, const int* in_sizes, int n_in,
                              void* d_out, int out_size) {
    const float* Q = (const float*)d_in[0];
    const float* K = (const float*)d_in[1];
    const float* V = (const float*)d_in[2];
    float* O = (float*)d_out;

    k_convert_kernel<<<N_BH * NKT, 256>>>(K);

    cudaFuncSetAttribute(sdpa_r9_kernel,
                         cudaFuncAttributeMaxDynamicSharedMemorySize, SMEM_BYTES);
    dim3 grid(S_LEN / TQ, N_BH);  // (16, 64)
    dim3 block(THREADS);
    sdpa_r9_kernel<<<grid, block, SMEM_BYTES>>>(Q, K, V, O);
}

// round 10
// speedup vs baseline: 1.1130x; 1.1130x over previous
#include <cuda_runtime.h>
#include <cuda_fp16.h>
#include <cstdint>

// SDPA B=4,H=16,S=2048,D=64 fp32. scores = QK^T * 4096 -> one-hot softmax.
// R10: kernel is smem-crossbar-byte-bound (R9: more warps -> no gain). Halve
// LDS bytes per query: each warp computes 32 queries (two m16 row tiles) that
// SHARE every K fragment load. CTA = 256 queries, grid.x halves -> total LDS
// traffic halves. Dropped write-only csq; epilogue reads ckq directly and
// parks exact scores in the drained cp.async staging ring.

#define S_LEN 2048
#define HDIM  64
#define TQ    256          // queries per CTA
#define THREADS 256        // 8 warps x 32 queries
#define TKT   64
#define NKT   (S_LEN / TKT)
#define N_BH  64
#define WINAPPROX 0.12f
#define LSCALE 4096.0f
#define NCAND 32

#define TILE_WORDS 2048                  // 8 KB per stage
#define NSTAGE 4

#define W_STG 0                                  // 8192 words (also epilogue es)
#define W_CK  (W_STG + NSTAGE * TILE_WORDS)      // int ck[256][NCAND] = 8192 words
#define W_CNT (W_CK + TQ * NCAND)                // int cnt[256]
#define SMEM_WORDS (W_CNT + TQ)
#define SMEM_BYTES (SMEM_WORDS * 4)              // ~66.6 KB

typedef unsigned long long u64;

__device__ static uint32_t g_kscr[(size_t)N_BH * NKT * TILE_WORDS];

__device__ __forceinline__ void mma_f16(float& d0, float& d1, float& d2, float& d3,
                                        uint32_t a0, uint32_t a1, uint32_t a2, uint32_t a3,
                                        uint32_t b0, uint32_t b1) {
    asm volatile(
        "mma.sync.aligned.m16n8k16.row.col.f32.f16.f16.f32 "
        "{%0,%1,%2,%3}, {%4,%5,%6,%7}, {%8,%9}, {%0,%1,%2,%3};"
        : "+f"(d0), "+f"(d1), "+f"(d2), "+f"(d3)
        : "r"(a0), "r"(a1), "r"(a2), "r"(a3), "r"(b0), "r"(b1));
}
__device__ __forceinline__ uint32_t f16x2(float lo, float hi) {
    uint32_t d;
    asm("cvt.rn.f16x2.f32 %0, %1, %2;" : "=r"(d) : "f"(hi), "f"(lo));
    return d;
}
__device__ __forceinline__ u64 ffma2(u64 a, u64 b, u64 c) {
    u64 d;
    asm("fma.rn.f32x2 %0, %1, %2, %3;" : "=l"(d) : "l"(a), "l"(b), "l"(c));
    return d;
}
__device__ __forceinline__ u64 fadd2(u64 a, u64 b) {
    u64 d;
    asm("add.rn.f32x2 %0, %1, %2;" : "=l"(d) : "l"(a), "l"(b));
    return d;
}
__device__ __forceinline__ float hsum2(u64 a) {
    float x, y;
    asm("mov.b64 {%0, %1}, %2;" : "=f"(x), "=f"(y) : "l"(a));
    return x + y;
}
__device__ __forceinline__ u64 pack2(float x, float y) {
    u64 d;
    asm("mov.b64 %0, {%1, %2};" : "=l"(d) : "f"(x), "f"(y));
    return d;
}
__device__ __forceinline__ void cp16(uint32_t saddr, const void* g) {
    asm volatile("cp.async.cg.shared.global [%0], [%1], 16;" :: "r"(saddr), "l"(g));
}

__global__ void __launch_bounds__(256)
k_convert_kernel(const float* __restrict__ K) {
    const int x = blockIdx.x;
    const int tid = threadIdx.x;
    const int bh = x / NKT, kt = x - bh * NKT;
    const float* kt_base = K + ((long)bh * S_LEN + (long)kt * TKT) * HDIM;
    uint32_t* dst = g_kscr + (size_t)x * TILE_WORDS;
#pragma unroll
    for (int i = 0; i < TILE_WORDS / 256; i++) {
        const int w = i * 256 + tid;
        const int b = w >> 7, iw = w & 127;
        const int nt = b >> 1, p = b & 1;
        const int n = nt * 8 + (iw >> 4);
        const int c = (iw >> 2) & 3, q = iw & 3;
        const int ks = 2 * p + (q >> 1);
        const int d2 = 8 * ks + 4 * (q & 1) + c;
        const float2 v = *(const float2*)(kt_base + n * HDIM + 2 * d2);
        dst[w] = f16x2(v.x, v.y);
    }
}

__global__ void __launch_bounds__(THREADS, 2)
sdpa_r10_kernel(const float* __restrict__ Q,
                const float* __restrict__ K,
                const float* __restrict__ V,
                float* __restrict__ O) {
    extern __shared__ float sm[];
    int* ckq  = (int*)(sm + W_CK);
    int* cntq = (int*)(sm + W_CNT);
    uint32_t sb;
    asm("{ .reg .u64 t; cvta.to.shared.u64 t, %1; cvt.u32.u64 %0, t; }" : "=r"(sb) : "l"(sm));

    const int tid  = threadIdx.x;
    const int lane = tid & 31;
    const int warp = tid >> 5;
    const int g    = lane >> 2;
    const int t    = lane & 3;
    const int bh   = blockIdx.y;
    const long bhoff = (long)bh * S_LEN * HDIM;
    const float* kb = K + bhoff;
    const float* vb = V + bhoff;
    const uint32_t* gsrc = g_kscr + (size_t)bh * NKT * TILE_WORDS;

    cntq[tid] = 0;

#pragma unroll
    for (int s = 0; s < NSTAGE - 1; s++) {
        const uint32_t sa = sb + (W_STG + s * TILE_WORDS) * 4 + tid * 32;
        const uint32_t* gp = gsrc + s * TILE_WORDS + tid * 8;
        cp16(sa, gp);
        cp16(sa + 16, gp + 4);
        asm volatile("cp.async.commit_group;" ::: "memory");
    }

    // ---- A fragments: warp's 32 query rows (rows w32+g, +8, +16, +24) ----
    uint32_t af[4][8];
    {
        const float* r0 = Q + ((long)bh * S_LEN + blockIdx.x * TQ + warp * 32 + g) * HDIM;
#pragma unroll
        for (int s = 0; s < 4; s++) {
            const int c = 16 * s + 2 * t;
            float2 v;
            v = *(const float2*)(r0 + c);                 af[s][0] = f16x2(v.x, v.y);
            v = *(const float2*)(r0 + 8 * HDIM + c);      af[s][1] = f16x2(v.x, v.y);
            v = *(const float2*)(r0 + c + 8);             af[s][2] = f16x2(v.x, v.y);
            v = *(const float2*)(r0 + 8 * HDIM + c + 8);  af[s][3] = f16x2(v.x, v.y);
            v = *(const float2*)(r0 + 16 * HDIM + c);     af[s][4] = f16x2(v.x, v.y);
            v = *(const float2*)(r0 + 24 * HDIM + c);     af[s][5] = f16x2(v.x, v.y);
            v = *(const float2*)(r0 + 16 * HDIM + c + 8); af[s][6] = f16x2(v.x, v.y);
            v = *(const float2*)(r0 + 24 * HDIM + c + 8); af[s][7] = f16x2(v.x, v.y);
        }
    }

    // 4 per-query scan states: queries w32+g +8 +16 +24
    float mq[4]  = {-INFINITY, -INFINITY, -INFINITY, -INFINITY};
    float thq[4] = {-INFINITY, -INFINITY, -INFINITY, -INFINITY};

    for (int kt = 0; kt < NKT; kt++) {
        asm volatile("cp.async.wait_group 2;" ::: "memory");
        __syncthreads();

        if (kt + 3 < NKT) {
            const int s = (kt + 3) & (NSTAGE - 1);
            const uint32_t sa = sb + (W_STG + s * TILE_WORDS) * 4 + tid * 32;
            const uint32_t* gp = gsrc + (kt + 3) * TILE_WORDS + tid * 8;
            cp16(sa, gp);
            cp16(sa + 16, gp + 4);
        }
        asm volatile("cp.async.commit_group;" ::: "memory");

        const uint32_t* sKB = (const uint32_t*)sm + W_STG + (kt & (NSTAGE - 1)) * TILE_WORDS;

        // ---- QK^T: 8 nt, each B fragment feeds BOTH query row tiles ----
        float acc[8][8];
#pragma unroll
        for (int nt = 0; nt < 8; nt++)
#pragma unroll
            for (int e = 0; e < 8; e++) acc[nt][e] = 0.0f;

#pragma unroll
        for (int p = 0; p < 2; p++) {
#pragma unroll
            for (int ng = 0; ng < 2; ng++) {
                uint4 bf[4];
#pragma unroll
                for (int i = 0; i < 4; i++)
                    bf[i] = *(const uint4*)(sKB + (((ng * 4 + i) * 2 + p) << 7) + lane * 4);
#pragma unroll
                for (int i = 0; i < 4; i++) {
                    const int nt = ng * 4 + i;
                    mma_f16(acc[nt][0], acc[nt][1], acc[nt][2], acc[nt][3],
                            af[2 * p][0], af[2 * p][1], af[2 * p][2], af[2 * p][3],
                            bf[i].x, bf[i].y);
                    mma_f16(acc[nt][4], acc[nt][5], acc[nt][6], acc[nt][7],
                            af[2 * p][4], af[2 * p][5], af[2 * p][6], af[2 * p][7],
                            bf[i].x, bf[i].y);
                }
#pragma unroll
                for (int i = 0; i < 4; i++) {
                    const int nt = ng * 4 + i;
                    mma_f16(acc[nt][0], acc[nt][1], acc[nt][2], acc[nt][3],
                            af[2 * p + 1][0], af[2 * p + 1][1],
                            af[2 * p + 1][2], af[2 * p + 1][3],
                            bf[i].z, bf[i].w);
                    mma_f16(acc[nt][4], acc[nt][5], acc[nt][6], acc[nt][7],
                            af[2 * p + 1][4], af[2 * p + 1][5],
                            af[2 * p + 1][6], af[2 * p + 1][7],
                            bf[i].z, bf[i].w);
                }
            }
        }

        // ---- in-register scan: 4 queries ----
        // pair base 2*qi: acc[nt][2qi]   = (query qi, key nt*8+2t)
        //                 acc[nt][2qi+1] = (query qi, key nt*8+2t+1)
        // qi order: 0->row g, 1->row g+8, 2->row g+16, 3->row g+24
        const int kbase = kt * TKT;
#pragma unroll
        for (int qi = 0; qi < 4; qi++) {
            float mx = fmaxf(acc[0][2 * qi], acc[0][2 * qi + 1]);
#pragma unroll
            for (int nt = 1; nt < 8; nt++)
                mx = fmaxf(mx, fmaxf(acc[nt][2 * qi], acc[nt][2 * qi + 1]));
            mx = fmaxf(mx, __shfl_xor_sync(0xFFFFFFFFu, mx, 1));
            mx = fmaxf(mx, __shfl_xor_sync(0xFFFFFFFFu, mx, 2));

            if (mx > thq[qi]) {   // rare
                mq[qi] = fmaxf(mq[qi], mx);
                thq[qi] = mq[qi] - WINAPPROX;
                const int q = warp * 32 + g + 8 * qi;
#pragma unroll
                for (int nt = 0; nt < 8; nt++) {
#pragma unroll
                    for (int e = 0; e < 2; e++) {
                        const float s = acc[nt][2 * qi + e];
                        if (s > thq[qi]) {
                            const int slot = atomicAdd(&cntq[q], 1);
                            if (slot < NCAND)
                                ckq[q * NCAND + slot] = kbase + nt * 8 + 2 * t + e;
                        }
                    }
                }
            }
        }
    }

    // drain cp.async before reusing staging ring for epilogue scores
    asm volatile("cp.async.wait_group 0;" ::: "memory");
    __syncthreads();

    // ---- epilogue: exact fp32 rescore (1 thread per query), softmax, V ----
    {
        float* es = sm + W_STG;   // [i*TQ + tid], 32 KB = NSTAGE*TILE_WORDS exactly

        const long qrow = (long)bh * S_LEN + blockIdx.x * TQ + tid;
        const u64* qg = (const u64*)(Q + qrow * HDIM);
        u64 q2[HDIM / 2];
#pragma unroll
        for (int j = 0; j < HDIM / 2; j++) q2[j] = qg[j];

        int nc = cntq[tid];
        if (nc > NCAND) nc = NCAND;
        float em = -INFINITY;
        for (int i = 0; i < nc; i++) {
            const int key = ckq[tid * NCAND + i];
            const u64* kr = (const u64*)(kb + (long)key * HDIM);
            u64 a0 = 0ULL, a1 = 0ULL, a2 = 0ULL, a3 = 0ULL;
#pragma unroll
            for (int j = 0; j < 8; j++) {
                a0 = ffma2(q2[4 * j + 0], kr[4 * j + 0], a0);
                a1 = ffma2(q2[4 * j + 1], kr[4 * j + 1], a1);
                a2 = ffma2(q2[4 * j + 2], kr[4 * j + 2], a2);
                a3 = ffma2(q2[4 * j + 3], kr[4 * j + 3], a3);
            }
            const float e = hsum2(fadd2(fadd2(a0, a1), fadd2(a2, a3)));
            es[i * TQ + tid] = e;
            em = fmaxf(em, e);
        }

        u64 o2[HDIM / 2];
#pragma unroll
        for (int j = 0; j < HDIM / 2; j++) o2[j] = 0ULL;
        float lsum = 0.0f;
        for (int i = 0; i < nc; i++) {
            const float w = __expf(LSCALE * (es[i * TQ + tid] - em));
            if (w > 1e-9f) {
                lsum += w;
                const u64* v2 = (const u64*)(vb + (long)ckq[tid * NCAND + i] * HDIM);
                const u64 w2 = pack2(w, w);
#pragma unroll
                for (int j = 0; j < HDIM / 2; j++) o2[j] = ffma2(w2, v2[j], o2[j]);
            }
        }
        const float inv = 1.0f / lsum;
        const u64 inv2 = pack2(inv, inv);
        u64* og = (u64*)(O + qrow * HDIM);
#pragma unroll
        for (int j = 0; j < HDIM / 2; j++) {
            u64 r;
            asm("mul.rn.f32x2 %0, %1, %2;" : "=l"(r) : "l"(o2[j]), "l"(inv2));
            og[j] = r;
        }
    }
}

extern "C" void kernel_launch(void* const* d_in, const int* in_sizes, int n_in,
                              void* d_out, int out_size) {
    const float* Q = (const float*)d_in[0];
    const float* K = (const float*)d_in[1];
    const float* V = (const float*)d_in[2];
    float* O = (float*)d_out;

    k_convert_kernel<<<N_BH * NKT, 256>>>(K);

    cudaFuncSetAttribute(sdpa_r10_kernel,
                         cudaFuncAttributeMaxDynamicSharedMemorySize, SMEM_BYTES);
    dim3 grid(S_LEN / TQ, N_BH);  // (8, 64)
    dim3 block(THREADS);
    sdpa_r10_kernel<<<grid, block, SMEM_BYTES>>>(Q, K, V, O);
}